// round 4
// baseline (speedup 1.0000x reference)
#include <cuda_runtime.h>
#include <cuda_bf16.h>
#include <cstdint>
#include <math.h>

// ---------------------------------------------------------------------------
// Problem constants
// ---------------------------------------------------------------------------
#define BB 4
#define TTOT 4096
#define CC 2048
#define NH 32
#define HS 64
#define ROWS (BB*TTOT)                    // 16384
#define ELEMS ((size_t)ROWS*(size_t)CC)   // 33,554,432
#define NCHUNK 8
#define TCH (TTOT/NCHUNK)                 // 512

typedef __nv_bfloat16 bf16;

// GEMM tiling
#define BM 128
#define BN 128
#define BKT 32                 // bf16 k elements per stage
#define ROWP 40                // padded row length (bf16) -> 80B stride
#define TILE_B (128*ROWP*2)    // 10240 bytes per plane tile
#define STAGE_B (4*TILE_B)     // 40960 bytes (Ah, Al, Bh, Bl)
#define NSTG 4
#define SMEM_B (NSTG*STAGE_B)  // 163840
#define KTILES (CC/BKT)        // 64

// ---------------------------------------------------------------------------
// Scratch
// ---------------------------------------------------------------------------
__device__ bf16 g_xr_h[ELEMS]; __device__ bf16 g_xr_l[ELEMS];
__device__ bf16 g_xk_h[ELEMS]; __device__ bf16 g_xk_l[ELEMS];
__device__ bf16 g_xv_h[ELEMS]; __device__ bf16 g_xv_l[ELEMS];
__device__ bf16 g_xg_h[ELEMS]; __device__ bf16 g_xg_l[ELEMS];
__device__ bf16 g_y_h[ELEMS];  __device__ bf16 g_y_l[ELEMS];
__device__ float g_r[ELEMS];
__device__ float g_k[ELEMS];
__device__ float g_v[ELEMS];
__device__ float g_g[ELEMS];
__device__ float g_ao[ELEMS];
// weights transposed to [N][K], split planes
__device__ bf16 g_Wr_h[CC*CC]; __device__ bf16 g_Wr_l[CC*CC];
__device__ bf16 g_Wk_h[CC*CC]; __device__ bf16 g_Wk_l[CC*CC];
__device__ bf16 g_Wv_h[CC*CC]; __device__ bf16 g_Wv_l[CC*CC];
__device__ bf16 g_Wg_h[CC*CC]; __device__ bf16 g_Wg_l[CC*CC];
__device__ bf16 g_Wo_h[CC*CC]; __device__ bf16 g_Wo_l[CC*CC];
// scan chunk scratch: [NCHUNK][128 bh][64][64]
__device__ float g_Sc[NCHUNK*128*HS*HS];
__device__ float g_S0c[NCHUNK*128*HS*HS];

// ---------------------------------------------------------------------------
// helpers
// ---------------------------------------------------------------------------
__device__ __forceinline__ uint32_t smem_u32(const void* p) {
    uint32_t a;
    asm("{ .reg .u64 t; cvta.to.shared.u64 t, %1; cvt.u32.u64 %0, t; }" : "=r"(a) : "l"(p));
    return a;
}
__device__ __forceinline__ void cpa16(uint32_t dst, const void* src) {
    asm volatile("cp.async.cg.shared.global [%0], [%1], 16;" :: "r"(dst), "l"(src));
}
__device__ __forceinline__ void cp_commit() {
    asm volatile("cp.async.commit_group;" ::: "memory");
}
template<int N> __device__ __forceinline__ void cp_wait() {
    asm volatile("cp.async.wait_group %0;" :: "n"(N) : "memory");
}
__device__ __forceinline__ void ldsm4(uint32_t (&r)[4], uint32_t addr) {
    asm volatile("ldmatrix.sync.aligned.m8n8.x4.shared.b16 {%0,%1,%2,%3}, [%4];"
                 : "=r"(r[0]), "=r"(r[1]), "=r"(r[2]), "=r"(r[3]) : "r"(addr));
}
__device__ __forceinline__ void mma_bf16(float (&c)[4], const uint32_t (&a)[4],
                                         uint32_t b0, uint32_t b1) {
    asm volatile(
        "mma.sync.aligned.m16n8k16.row.col.f32.bf16.bf16.f32 "
        "{%0,%1,%2,%3}, {%4,%5,%6,%7}, {%8,%9}, {%0,%1,%2,%3};"
        : "+f"(c[0]), "+f"(c[1]), "+f"(c[2]), "+f"(c[3])
        : "r"(a[0]), "r"(a[1]), "r"(a[2]), "r"(a[3]), "r"(b0), "r"(b1));
}
__device__ __forceinline__ void split_bf16(float x, bf16& h, bf16& l) {
    h = __float2bfloat16_rn(x);
    l = __float2bfloat16_rn(x - __bfloat162float(h));
}

// ---------------------------------------------------------------------------
// 1) Token-shift mixing -> bf16 hi/lo planes
// ---------------------------------------------------------------------------
__global__ void mix_kernel(const float* __restrict__ x,
                           const float* __restrict__ tmk, const float* __restrict__ tmv,
                           const float* __restrict__ tmr, const float* __restrict__ tmg,
                           bf16* __restrict__ xkh, bf16* __restrict__ xkl,
                           bf16* __restrict__ xvh, bf16* __restrict__ xvl,
                           bf16* __restrict__ xrh, bf16* __restrict__ xrl,
                           bf16* __restrict__ xgh, bf16* __restrict__ xgl) {
    size_t idx = (size_t)blockIdx.x * blockDim.x + threadIdx.x;
    if (idx >= ELEMS) return;
    int c = (int)(idx % CC);
    int t = (int)((idx / CC) % TTOT);
    float xc = x[idx];
    float xp = (t == 0) ? 0.0f : x[idx - CC];
    float mk = tmk[c], mv = tmv[c], mr = tmr[c], mg = tmg[c];
    float vk = xc * mk + xp * (1.0f - mk);
    float vv = xc * mv + xp * (1.0f - mv);
    float vr = xc * mr + xp * (1.0f - mr);
    float vg = xc * mg + xp * (1.0f - mg);
    bf16 h, l;
    split_bf16(vk, h, l); xkh[idx] = h; xkl[idx] = l;
    split_bf16(vv, h, l); xvh[idx] = h; xvl[idx] = l;
    split_bf16(vr, h, l); xrh[idx] = h; xrl[idx] = l;
    split_bf16(vg, h, l); xgh[idx] = h; xgl[idx] = l;
}

// ---------------------------------------------------------------------------
// 2) Weight prep: transpose [K,N] -> [N,K], split bf16 hi/lo
// ---------------------------------------------------------------------------
__global__ void wprep_kernel(const float* __restrict__ W,
                             bf16* __restrict__ hiT, bf16* __restrict__ loT) {
    __shared__ float t[32][33];
    int n0 = blockIdx.x * 32, k0 = blockIdx.y * 32;
    int tx = threadIdx.x, ty = threadIdx.y;
    #pragma unroll
    for (int r = ty; r < 32; r += 8)
        t[r][tx] = W[(size_t)(k0 + r) * CC + n0 + tx];
    __syncthreads();
    #pragma unroll
    for (int r = ty; r < 32; r += 8) {
        float v = t[tx][r];                 // W[k0+tx][n0+r]
        size_t o = (size_t)(n0 + r) * CC + k0 + tx;
        bf16 h, l; split_bf16(v, h, l);
        hiT[o] = h; loT[o] = l;
    }
}

// ---------------------------------------------------------------------------
// 3) bf16 split GEMM: C[M,2048] = A @ B^T, A planes [M,K], B planes [N,K].
//    3 products: Ah*Bh + Ah*Bl + Al*Bh, fp32 accum via mma.sync m16n8k16.
//    4-stage cp.async pipeline, ONE __syncthreads per k-tile.
// ---------------------------------------------------------------------------
__global__ __launch_bounds__(256, 1) void tc_gemm(
        const bf16* __restrict__ Ah, const bf16* __restrict__ Al,
        const bf16* __restrict__ Bh, const bf16* __restrict__ Bl,
        float* __restrict__ C, int act) {
    extern __shared__ char smem[];
    uint32_t sb = smem_u32(smem);

    int tid = threadIdx.x;
    int lane = tid & 31;
    int wm = (tid >> 5) & 3;      // warp m index 0..3
    int wn = tid >> 7;            // warp n index 0..1
    int mBase = blockIdx.y * BM;
    int nBase = blockIdx.x * BN;

    // Precompute cp.async assignments: 2048 16B-chunks/stage, 8 per thread.
    // id -> tile(0:Ah 1:Al 2:Bh 3:Bl), row rid (0..127), chunk ch (0..3)
    const bf16* planes[4] = {Ah, Al, Bh, Bl};
    int rowbase[4] = {mBase, mBase, nBase, nBase};
    const bf16* srcp[8];
    uint32_t dstoff[8];
    #pragma unroll
    for (int i = 0; i < 8; i++) {
        int id = tid + i * 256;
        int tile = id >> 9;
        int rid = (id & 511) >> 2;
        int ch = id & 3;
        srcp[i] = planes[tile] + (size_t)(rowbase[tile] + rid) * CC + ch * 8;
        dstoff[i] = (uint32_t)(tile * TILE_B + rid * 80 + ch * 16);
    }

    float acc[2][8][4];
    #pragma unroll
    for (int i = 0; i < 2; i++)
        #pragma unroll
        for (int j = 0; j < 8; j++)
            #pragma unroll
            for (int q = 0; q < 4; q++) acc[i][j][q] = 0.0f;

    // prologue: fill stages 0..NSTG-2 (one commit group each)
    #pragma unroll
    for (int s = 0; s < NSTG - 1; s++) {
        uint32_t stb = sb + s * STAGE_B;
        #pragma unroll
        for (int i = 0; i < 8; i++)
            cpa16(stb + dstoff[i], srcp[i] + s * BKT);
        cp_commit();
    }

    // lane addressing offsets (bytes) for ldmatrix
    uint32_t aRow = (uint32_t)(wm * 32 + ((lane >> 3) & 1) * 8 + (lane & 7));
    uint32_t aCol = (uint32_t)((lane >> 4) * 16);
    uint32_t bRow = (uint32_t)(wn * 64 + (lane >> 4) * 8 + (lane & 7));
    uint32_t bCol = (uint32_t)(((lane >> 3) & 1) * 16);

    for (int kt = 0; kt < KTILES; kt++) {
        cp_wait<NSTG - 2>();     // tile kt resident
        __syncthreads();

        // prefetch tile kt+NSTG-1 into stage (kt+NSTG-1)%NSTG == (kt-1)%NSTG
        int nt = kt + NSTG - 1;
        if (nt < KTILES) {
            uint32_t stb = sb + (nt & (NSTG - 1)) * STAGE_B;
            #pragma unroll
            for (int i = 0; i < 8; i++)
                cpa16(stb + dstoff[i], srcp[i] + nt * BKT);
        }
        cp_commit();             // commit (possibly empty) to keep group counts aligned

        uint32_t stg = sb + (kt & (NSTG - 1)) * STAGE_B;
        #pragma unroll
        for (int ks = 0; ks < 2; ks++) {
            uint32_t a_h[2][4], a_l[2][4];
            #pragma unroll
            for (int mi = 0; mi < 2; mi++) {
                uint32_t ra = (aRow + mi * 16) * 80 + aCol + ks * 32;
                ldsm4(a_h[mi], stg + 0 * TILE_B + ra);
                ldsm4(a_l[mi], stg + 1 * TILE_B + ra);
            }
            #pragma unroll
            for (int njp = 0; njp < 4; njp++) {
                uint32_t rb = (bRow + njp * 16) * 80 + bCol + ks * 32;
                uint32_t b_h[4], b_l[4];
                ldsm4(b_h, stg + 2 * TILE_B + rb);
                ldsm4(b_l, stg + 3 * TILE_B + rb);
                #pragma unroll
                for (int mi = 0; mi < 2; mi++) {
                    #pragma unroll
                    for (int q = 0; q < 2; q++) {
                        int ni = njp * 2 + q;
                        mma_bf16(acc[mi][ni], a_h[mi], b_h[2*q], b_h[2*q+1]);
                        mma_bf16(acc[mi][ni], a_h[mi], b_l[2*q], b_l[2*q+1]);
                        mma_bf16(acc[mi][ni], a_l[mi], b_h[2*q], b_h[2*q+1]);
                    }
                }
            }
        }
    }

    // epilogue
    int mrow = mBase + wm * 32 + (lane >> 2);
    int ncol = nBase + wn * 64 + (lane & 3) * 2;
    #pragma unroll
    for (int mi = 0; mi < 2; mi++) {
        #pragma unroll
        for (int ni = 0; ni < 8; ni++) {
            float v0 = acc[mi][ni][0], v1 = acc[mi][ni][1];
            float v2 = acc[mi][ni][2], v3 = acc[mi][ni][3];
            if (act) {
                v0 = v0 / (1.0f + expf(-v0));
                v1 = v1 / (1.0f + expf(-v1));
                v2 = v2 / (1.0f + expf(-v2));
                v3 = v3 / (1.0f + expf(-v3));
            }
            float* p0 = C + (size_t)(mrow + mi * 16) * CC + ncol + ni * 8;
            float* p1 = p0 + 8 * CC;
            *(float2*)p0 = make_float2(v0, v1);
            *(float2*)p1 = make_float2(v2, v3);
        }
    }
}

// ---------------------------------------------------------------------------
// 4) Chunked RWKV scan
// ---------------------------------------------------------------------------
__global__ __launch_bounds__(HS) void scanA_kernel(
        const float* __restrict__ k, const float* __restrict__ v,
        const float* __restrict__ td, float* __restrict__ Sc) {
    int bh = blockIdx.x;
    int chunk = blockIdx.y;
    int b = bh >> 5, h = bh & 31;
    int j = threadIdx.x;

    float w = expf(-expf(td[h]));
    float S[HS];
    #pragma unroll
    for (int a = 0; a < HS; a++) S[a] = 0.0f;

    __shared__ float sk[HS], sv[HS];
    size_t base = (size_t)b * TTOT * CC + (size_t)h * HS;
    int t0 = chunk * TCH;

    for (int t = t0; t < t0 + TCH; t++) {
        size_t off = base + (size_t)t * CC;
        sk[j] = k[off + j];
        sv[j] = v[off + j];
        __syncthreads();
        float vj = sv[j];
        #pragma unroll
        for (int a = 0; a < HS; a++)
            S[a] = fmaf(w, S[a], sk[a] * vj);
        __syncthreads();
    }
    size_t o = ((size_t)(chunk * 128 + bh) * HS) * HS + j;
    #pragma unroll
    for (int a = 0; a < HS; a++)
        Sc[o + (size_t)a * HS] = S[a];
}

__global__ __launch_bounds__(HS) void scanB_kernel(
        const float* __restrict__ s0, const float* __restrict__ Sc,
        const float* __restrict__ td, float* __restrict__ S0c) {
    int bh = blockIdx.x;
    int h = bh & 31;
    int j = threadIdx.x;
    float wT = expf(-expf(td[h]) * (float)TCH);

    float s[HS];
    #pragma unroll
    for (int a = 0; a < HS; a++)
        s[a] = s0[((size_t)bh * HS + a) * HS + j];

    for (int c = 0; c < NCHUNK; c++) {
        size_t o = ((size_t)(c * 128 + bh) * HS) * HS + j;
        #pragma unroll
        for (int a = 0; a < HS; a++) {
            S0c[o + (size_t)a * HS] = s[a];
            s[a] = fmaf(wT, s[a], Sc[o + (size_t)a * HS]);
        }
    }
}

__global__ __launch_bounds__(HS) void scanC_kernel(
        const float* __restrict__ r, const float* __restrict__ k,
        const float* __restrict__ v, const float* __restrict__ td,
        const float* __restrict__ tf, const float* __restrict__ S0c,
        float* __restrict__ out) {
    int bh = blockIdx.x;
    int chunk = blockIdx.y;
    int b = bh >> 5, h = bh & 31;
    int j = threadIdx.x;

    float w = expf(-expf(td[h]));
    float u = tf[h];

    float s[HS];
    size_t o = ((size_t)(chunk * 128 + bh) * HS) * HS + j;
    #pragma unroll
    for (int a = 0; a < HS; a++)
        s[a] = S0c[o + (size_t)a * HS];

    __shared__ float sr[HS], sk[HS], sv[HS];
    size_t base = (size_t)b * TTOT * CC + (size_t)h * HS;
    int t0 = chunk * TCH;

    for (int t = t0; t < t0 + TCH; t++) {
        size_t off = base + (size_t)t * CC;
        sr[j] = r[off + j];
        sk[j] = k[off + j];
        sv[j] = v[off + j];
        __syncthreads();
        float vj = sv[j];
        float kr = 0.0f, oacc = 0.0f;
        #pragma unroll
        for (int a = 0; a < HS; a++) {
            float ra = sr[a], ka = sk[a];
            kr = fmaf(ra, ka, kr);
            oacc = fmaf(ra, s[a], oacc);
            s[a] = fmaf(w, s[a], ka * vj);
        }
        oacc = fmaf(u * kr, vj, oacc);
        out[off + j] = oacc;
        __syncthreads();
    }
}

// ---------------------------------------------------------------------------
// 5) GroupNorm * gamma + beta, * g -> bf16 hi/lo of y
// ---------------------------------------------------------------------------
__global__ void gn_mul_kernel(const float* __restrict__ x, const float* __restrict__ g,
                              const float* __restrict__ gamma, const float* __restrict__ beta,
                              bf16* __restrict__ yh, bf16* __restrict__ yl) {
    int warp = (int)((blockIdx.x * blockDim.x + threadIdx.x) >> 5);
    int lane = threadIdx.x & 31;
    if (warp >= ROWS * NH) return;
    int row = warp >> 5;
    int h   = warp & 31;
    size_t base = (size_t)row * CC + (size_t)h * HS;

    float x0 = x[base + lane]      * 0.125f;
    float x1 = x[base + lane + 32] * 0.125f;
    float sum = x0 + x1;
    float sq  = fmaf(x0, x0, x1 * x1);
    #pragma unroll
    for (int o = 16; o; o >>= 1) {
        sum += __shfl_xor_sync(0xffffffffu, sum, o);
        sq  += __shfl_xor_sync(0xffffffffu, sq,  o);
    }
    float mu  = sum * (1.0f / 64.0f);
    float var = sq  * (1.0f / 64.0f) - mu * mu;
    float inv = rsqrtf(var + 1e-5f);

    int c0 = h * HS + lane, c1 = c0 + 32;
    float y0 = ((x0 - mu) * inv * gamma[c0] + beta[c0]) * g[base + lane];
    float y1 = ((x1 - mu) * inv * gamma[c1] + beta[c1]) * g[base + lane + 32];
    bf16 hh, ll;
    split_bf16(y0, hh, ll); yh[base + lane]      = hh; yl[base + lane]      = ll;
    split_bf16(y1, hh, ll); yh[base + lane + 32] = hh; yl[base + lane + 32] = ll;
}

// ---------------------------------------------------------------------------
// Launcher
// ---------------------------------------------------------------------------
extern "C" void kernel_launch(void* const* d_in, const int* in_sizes, int n_in,
                              void* d_out, int out_size) {
    const float* x     = (const float*)d_in[0];
    const float* Wr    = (const float*)d_in[1];
    const float* Wk    = (const float*)d_in[2];
    const float* Wv    = (const float*)d_in[3];
    const float* Wg    = (const float*)d_in[4];
    const float* Wo    = (const float*)d_in[5];
    const float* gamma = (const float*)d_in[6];
    const float* beta  = (const float*)d_in[7];
    const float* tmk   = (const float*)d_in[8];
    const float* tmv   = (const float*)d_in[9];
    const float* tmr   = (const float*)d_in[10];
    const float* tmg   = (const float*)d_in[11];
    const float* td    = (const float*)d_in[12];
    const float* tf    = (const float*)d_in[13];
    const float* s0    = (const float*)d_in[14];
    float* out = (float*)d_out;

    static bool attr_done = false;
    if (!attr_done) {
        cudaFuncSetAttribute(tc_gemm, cudaFuncAttributeMaxDynamicSharedMemorySize, SMEM_B);
        attr_done = true;
    }

    bf16 *xrh,*xrl,*xkh,*xkl,*xvh,*xvl,*xgh,*xgl,*yh,*yl;
    bf16 *wrh,*wrl,*wkh,*wkl,*wvh,*wvl,*wgh,*wgl,*woh,*wol;
    float *rb,*kb,*vb,*gb,*ao,*Sc,*S0c;
    cudaGetSymbolAddress((void**)&xrh, g_xr_h); cudaGetSymbolAddress((void**)&xrl, g_xr_l);
    cudaGetSymbolAddress((void**)&xkh, g_xk_h); cudaGetSymbolAddress((void**)&xkl, g_xk_l);
    cudaGetSymbolAddress((void**)&xvh, g_xv_h); cudaGetSymbolAddress((void**)&xvl, g_xv_l);
    cudaGetSymbolAddress((void**)&xgh, g_xg_h); cudaGetSymbolAddress((void**)&xgl, g_xg_l);
    cudaGetSymbolAddress((void**)&yh,  g_y_h);  cudaGetSymbolAddress((void**)&yl,  g_y_l);
    cudaGetSymbolAddress((void**)&rb, g_r); cudaGetSymbolAddress((void**)&kb, g_k);
    cudaGetSymbolAddress((void**)&vb, g_v); cudaGetSymbolAddress((void**)&gb, g_g);
    cudaGetSymbolAddress((void**)&ao, g_ao);
    cudaGetSymbolAddress((void**)&Sc, g_Sc); cudaGetSymbolAddress((void**)&S0c, g_S0c);
    cudaGetSymbolAddress((void**)&wrh, g_Wr_h); cudaGetSymbolAddress((void**)&wrl, g_Wr_l);
    cudaGetSymbolAddress((void**)&wkh, g_Wk_h); cudaGetSymbolAddress((void**)&wkl, g_Wk_l);
    cudaGetSymbolAddress((void**)&wvh, g_Wv_h); cudaGetSymbolAddress((void**)&wvl, g_Wv_l);
    cudaGetSymbolAddress((void**)&wgh, g_Wg_h); cudaGetSymbolAddress((void**)&wgl, g_Wg_l);
    cudaGetSymbolAddress((void**)&woh, g_Wo_h); cudaGetSymbolAddress((void**)&wol, g_Wo_l);

    // weight transpose + split
    dim3 wg2(CC / 32, CC / 32), wb2(32, 8);
    wprep_kernel<<<wg2, wb2>>>(Wr, wrh, wrl);
    wprep_kernel<<<wg2, wb2>>>(Wk, wkh, wkl);
    wprep_kernel<<<wg2, wb2>>>(Wv, wvh, wvl);
    wprep_kernel<<<wg2, wb2>>>(Wg, wgh, wgl);
    wprep_kernel<<<wg2, wb2>>>(Wo, woh, wol);

    // token-shift mix + split
    {
        int threads = 256;
        int blocks = (int)((ELEMS + threads - 1) / threads);
        mix_kernel<<<blocks, threads>>>(x, tmk, tmv, tmr, tmg,
                                        xkh, xkl, xvh, xvl, xrh, xrl, xgh, xgl);
    }

    // projections
    dim3 gg(CC / BN, ROWS / BM);
    tc_gemm<<<gg, 256, SMEM_B>>>(xrh, xrl, wrh, wrl, rb, 0);
    tc_gemm<<<gg, 256, SMEM_B>>>(xkh, xkl, wkh, wkl, kb, 0);
    tc_gemm<<<gg, 256, SMEM_B>>>(xvh, xvl, wvh, wvl, vb, 0);
    tc_gemm<<<gg, 256, SMEM_B>>>(xgh, xgl, wgh, wgl, gb, 1);   // silu

    // chunked scan
    dim3 sg(128, NCHUNK);
    scanA_kernel<<<sg, HS>>>(kb, vb, td, Sc);
    scanB_kernel<<<128, HS>>>(s0, Sc, td, S0c);
    scanC_kernel<<<sg, HS>>>(rb, kb, vb, td, tf, S0c, ao);

    // groupnorm + gate -> y planes
    gn_mul_kernel<<<(ROWS * NH) / 8, 256>>>(ao, gb, gamma, beta, yh, yl);

    // output projection
    tc_gemm<<<gg, 256, SMEM_B>>>(yh, yl, woh, wol, out, 0);
}

// round 5
// speedup vs baseline: 2.3905x; 2.3905x over previous
#include <cuda_runtime.h>
#include <cuda_fp16.h>
#include <cstdint>
#include <math.h>

// ---------------------------------------------------------------------------
// Problem constants
// ---------------------------------------------------------------------------
#define BB 4
#define TTOT 4096
#define CC 2048
#define NH 32
#define HS 64
#define ROWS (BB*TTOT)                    // 16384
#define ELEMS ((size_t)ROWS*(size_t)CC)   // 33,554,432
#define NCHUNK 8
#define TCH (TTOT/NCHUNK)                 // 512

typedef __half f16;

// GEMM tiling
#define BM 128
#define BN 128
#define BKT 32                 // fp16 k elements per stage
#define TILE_B (128*80)        // 10240 bytes per plane tile (80B padded rows)
#define STAGE_B (3*TILE_B)     // 30720 bytes (Ahi, Alo, B)
#define NSTG 3
#define SMEM_B (NSTG*STAGE_B)  // 92160
#define KTILES (CC/BKT)        // 64

// ---------------------------------------------------------------------------
// Scratch
// ---------------------------------------------------------------------------
__device__ f16 g_xr_h[ELEMS]; __device__ f16 g_xr_l[ELEMS];
__device__ f16 g_xk_h[ELEMS]; __device__ f16 g_xk_l[ELEMS];
__device__ f16 g_xv_h[ELEMS]; __device__ f16 g_xv_l[ELEMS];
__device__ f16 g_xg_h[ELEMS]; __device__ f16 g_xg_l[ELEMS];
__device__ f16 g_y_h[ELEMS];  __device__ f16 g_y_l[ELEMS];
__device__ float g_r[ELEMS];
__device__ float g_k[ELEMS];
__device__ float g_v[ELEMS];
__device__ float g_g[ELEMS];
__device__ float g_ao[ELEMS];
// weights transposed to [N][K], single fp16 plane
__device__ f16 g_WrT[CC*CC];
__device__ f16 g_WkT[CC*CC];
__device__ f16 g_WvT[CC*CC];
__device__ f16 g_WgT[CC*CC];
__device__ f16 g_WoT[CC*CC];
// scan chunk scratch
__device__ float g_Sc[NCHUNK*128*HS*HS];
__device__ float g_S0c[NCHUNK*128*HS*HS];

// ---------------------------------------------------------------------------
// helpers
// ---------------------------------------------------------------------------
__device__ __forceinline__ uint32_t smem_u32(const void* p) {
    uint32_t a;
    asm("{ .reg .u64 t; cvta.to.shared.u64 t, %1; cvt.u32.u64 %0, t; }" : "=r"(a) : "l"(p));
    return a;
}
__device__ __forceinline__ void cpa16(uint32_t dst, const void* src) {
    asm volatile("cp.async.cg.shared.global [%0], [%1], 16;" :: "r"(dst), "l"(src));
}
__device__ __forceinline__ void cp_commit() {
    asm volatile("cp.async.commit_group;" ::: "memory");
}
template<int N> __device__ __forceinline__ void cp_wait() {
    asm volatile("cp.async.wait_group %0;" :: "n"(N) : "memory");
}
__device__ __forceinline__ void ldsm4(uint32_t (&r)[4], uint32_t addr) {
    asm volatile("ldmatrix.sync.aligned.m8n8.x4.shared.b16 {%0,%1,%2,%3}, [%4];"
                 : "=r"(r[0]), "=r"(r[1]), "=r"(r[2]), "=r"(r[3]) : "r"(addr));
}
__device__ __forceinline__ void mma_f16(float (&c)[4], const uint32_t (&a)[4],
                                        uint32_t b0, uint32_t b1) {
    asm volatile(
        "mma.sync.aligned.m16n8k16.row.col.f32.f16.f16.f32 "
        "{%0,%1,%2,%3}, {%4,%5,%6,%7}, {%8,%9}, {%0,%1,%2,%3};"
        : "+f"(c[0]), "+f"(c[1]), "+f"(c[2]), "+f"(c[3])
        : "r"(a[0]), "r"(a[1]), "r"(a[2]), "r"(a[3]), "r"(b0), "r"(b1));
}
__device__ __forceinline__ void split_f16(float x, f16& h, f16& l) {
    h = __float2half_rn(x);
    l = __float2half_rn(x - __half2float(h));
}

// ---------------------------------------------------------------------------
// 1) Token-shift mixing -> fp16 hi/lo planes
// ---------------------------------------------------------------------------
__global__ void mix_kernel(const float* __restrict__ x,
                           const float* __restrict__ tmk, const float* __restrict__ tmv,
                           const float* __restrict__ tmr, const float* __restrict__ tmg,
                           f16* __restrict__ xkh, f16* __restrict__ xkl,
                           f16* __restrict__ xvh, f16* __restrict__ xvl,
                           f16* __restrict__ xrh, f16* __restrict__ xrl,
                           f16* __restrict__ xgh, f16* __restrict__ xgl) {
    size_t idx = (size_t)blockIdx.x * blockDim.x + threadIdx.x;
    if (idx >= ELEMS) return;
    int c = (int)(idx % CC);
    int t = (int)((idx / CC) % TTOT);
    float xc = x[idx];
    float xp = (t == 0) ? 0.0f : x[idx - CC];
    float mk = tmk[c], mv = tmv[c], mr = tmr[c], mg = tmg[c];
    float vk = xc * mk + xp * (1.0f - mk);
    float vv = xc * mv + xp * (1.0f - mv);
    float vr = xc * mr + xp * (1.0f - mr);
    float vg = xc * mg + xp * (1.0f - mg);
    f16 h, l;
    split_f16(vk, h, l); xkh[idx] = h; xkl[idx] = l;
    split_f16(vv, h, l); xvh[idx] = h; xvl[idx] = l;
    split_f16(vr, h, l); xrh[idx] = h; xrl[idx] = l;
    split_f16(vg, h, l); xgh[idx] = h; xgl[idx] = l;
}

// ---------------------------------------------------------------------------
// 2) Weight prep: transpose [K,N] -> [N,K], single fp16 plane
// ---------------------------------------------------------------------------
__global__ void wprep_kernel(const float* __restrict__ W, f16* __restrict__ WT) {
    __shared__ float t[32][33];
    int n0 = blockIdx.x * 32, k0 = blockIdx.y * 32;
    int tx = threadIdx.x, ty = threadIdx.y;
    #pragma unroll
    for (int r = ty; r < 32; r += 8)
        t[r][tx] = W[(size_t)(k0 + r) * CC + n0 + tx];
    __syncthreads();
    #pragma unroll
    for (int r = ty; r < 32; r += 8)
        WT[(size_t)(n0 + r) * CC + k0 + tx] = __float2half_rn(t[tx][r]);
}

// ---------------------------------------------------------------------------
// 3) fp16 split GEMM: C[M,2048] = A @ B^T.
//    A as fp16 hi/lo planes [M,K], B single fp16 plane [N,K].
//    2 products: Ah*B + Al*B, fp32 accum via mma.sync m16n8k16.
//    3-stage cp.async pipeline, 1 sync/tile, 2 CTAs/SM.
// ---------------------------------------------------------------------------
__global__ __launch_bounds__(256, 2) void tc_gemm(
        const f16* __restrict__ Ah, const f16* __restrict__ Al,
        const f16* __restrict__ B, float* __restrict__ C, int act) {
    extern __shared__ char smem[];
    uint32_t sb = smem_u32(smem);

    int tid = threadIdx.x;
    int lane = tid & 31;
    int wm = (tid >> 5) & 3;      // warp m index 0..3
    int wn = tid >> 7;            // warp n index 0..1
    int mBase = blockIdx.y * BM;
    int nBase = blockIdx.x * BN;

    // cp.async assignments: 1536 16B-chunks/stage, 6 per thread.
    // id -> tile(0:Ah 1:Al 2:B), row rid (0..127), chunk ch (0..3)
    const f16* planes[3] = {Ah, Al, B};
    int rowbase[3] = {mBase, mBase, nBase};
    const f16* srcp[6];
    uint32_t dstoff[6];
    #pragma unroll
    for (int i = 0; i < 6; i++) {
        int id = tid + i * 256;
        int tile = id >> 9;
        int rid = (id & 511) >> 2;
        int ch = id & 3;
        srcp[i] = planes[tile] + (size_t)(rowbase[tile] + rid) * CC + ch * 8;
        dstoff[i] = (uint32_t)(tile * TILE_B + rid * 80 + ch * 16);
    }

    float acc[2][8][4];
    #pragma unroll
    for (int i = 0; i < 2; i++)
        #pragma unroll
        for (int j = 0; j < 8; j++)
            #pragma unroll
            for (int q = 0; q < 4; q++) acc[i][j][q] = 0.0f;

    // prologue: fill stages 0,1
    #pragma unroll
    for (int s = 0; s < NSTG - 1; s++) {
        uint32_t stb = sb + s * STAGE_B;
        #pragma unroll
        for (int i = 0; i < 6; i++)
            cpa16(stb + dstoff[i], srcp[i] + s * BKT);
        cp_commit();
    }

    // lane addressing (bytes) for ldmatrix
    uint32_t aRow = (uint32_t)(wm * 32 + ((lane >> 3) & 1) * 8 + (lane & 7));
    uint32_t aCol = (uint32_t)((lane >> 4) * 16);
    uint32_t bRow = (uint32_t)(wn * 64 + (lane >> 4) * 8 + (lane & 7));
    uint32_t bCol = (uint32_t)(((lane >> 3) & 1) * 16);

    int stgIdx = 0;      // stage of tile kt
    for (int kt = 0; kt < KTILES; kt++) {
        cp_wait<1>();          // tile kt resident
        __syncthreads();

        // prefetch tile kt+2 into stage (kt+2)%3 (consumed in iter kt-1; safe)
        int nt = kt + NSTG - 1;
        int pfs = stgIdx + (NSTG - 1); if (pfs >= NSTG) pfs -= NSTG;
        if (nt < KTILES) {
            uint32_t stb = sb + pfs * STAGE_B;
            #pragma unroll
            for (int i = 0; i < 6; i++)
                cpa16(stb + dstoff[i], srcp[i] + nt * BKT);
        }
        cp_commit();

        uint32_t stg = sb + stgIdx * STAGE_B;
        if (++stgIdx == NSTG) stgIdx = 0;

        #pragma unroll
        for (int ks = 0; ks < 2; ks++) {
            uint32_t a_h[2][4], a_l[2][4];
            #pragma unroll
            for (int mi = 0; mi < 2; mi++) {
                uint32_t ra = (aRow + mi * 16) * 80 + aCol + ks * 32;
                ldsm4(a_h[mi], stg + 0 * TILE_B + ra);
                ldsm4(a_l[mi], stg + 1 * TILE_B + ra);
            }
            #pragma unroll
            for (int njp = 0; njp < 4; njp++) {
                uint32_t rb = (bRow + njp * 16) * 80 + bCol + ks * 32;
                uint32_t b_f[4];
                ldsm4(b_f, stg + 2 * TILE_B + rb);
                #pragma unroll
                for (int mi = 0; mi < 2; mi++) {
                    #pragma unroll
                    for (int q = 0; q < 2; q++) {
                        int ni = njp * 2 + q;
                        mma_f16(acc[mi][ni], a_h[mi], b_f[2*q], b_f[2*q+1]);
                        mma_f16(acc[mi][ni], a_l[mi], b_f[2*q], b_f[2*q+1]);
                    }
                }
            }
        }
    }

    // epilogue
    int mrow = mBase + wm * 32 + (lane >> 2);
    int ncol = nBase + wn * 64 + (lane & 3) * 2;
    #pragma unroll
    for (int mi = 0; mi < 2; mi++) {
        #pragma unroll
        for (int ni = 0; ni < 8; ni++) {
            float v0 = acc[mi][ni][0], v1 = acc[mi][ni][1];
            float v2 = acc[mi][ni][2], v3 = acc[mi][ni][3];
            if (act) {
                v0 = v0 / (1.0f + expf(-v0));
                v1 = v1 / (1.0f + expf(-v1));
                v2 = v2 / (1.0f + expf(-v2));
                v3 = v3 / (1.0f + expf(-v3));
            }
            float* p0 = C + (size_t)(mrow + mi * 16) * CC + ncol + ni * 8;
            float* p1 = p0 + 8 * CC;
            *(float2*)p0 = make_float2(v0, v1);
            *(float2*)p1 = make_float2(v2, v3);
        }
    }
}

// ---------------------------------------------------------------------------
// 4) Chunked RWKV scan
// ---------------------------------------------------------------------------
__global__ __launch_bounds__(HS) void scanA_kernel(
        const float* __restrict__ k, const float* __restrict__ v,
        const float* __restrict__ td, float* __restrict__ Sc) {
    int bh = blockIdx.x;
    int chunk = blockIdx.y;
    int b = bh >> 5, h = bh & 31;
    int j = threadIdx.x;

    float w = expf(-expf(td[h]));
    float S[HS];
    #pragma unroll
    for (int a = 0; a < HS; a++) S[a] = 0.0f;

    __shared__ float sk[HS], sv[HS];
    size_t base = (size_t)b * TTOT * CC + (size_t)h * HS;
    int t0 = chunk * TCH;

    for (int t = t0; t < t0 + TCH; t++) {
        size_t off = base + (size_t)t * CC;
        sk[j] = k[off + j];
        sv[j] = v[off + j];
        __syncthreads();
        float vj = sv[j];
        #pragma unroll
        for (int a = 0; a < HS; a++)
            S[a] = fmaf(w, S[a], sk[a] * vj);
        __syncthreads();
    }
    size_t o = ((size_t)(chunk * 128 + bh) * HS) * HS + j;
    #pragma unroll
    for (int a = 0; a < HS; a++)
        Sc[o + (size_t)a * HS] = S[a];
}

__global__ __launch_bounds__(HS) void scanB_kernel(
        const float* __restrict__ s0, const float* __restrict__ Sc,
        const float* __restrict__ td, float* __restrict__ S0c) {
    int bh = blockIdx.x;
    int h = bh & 31;
    int j = threadIdx.x;
    float wT = expf(-expf(td[h]) * (float)TCH);

    float s[HS];
    #pragma unroll
    for (int a = 0; a < HS; a++)
        s[a] = s0[((size_t)bh * HS + a) * HS + j];

    for (int c = 0; c < NCHUNK; c++) {
        size_t o = ((size_t)(c * 128 + bh) * HS) * HS + j;
        #pragma unroll
        for (int a = 0; a < HS; a++) {
            S0c[o + (size_t)a * HS] = s[a];
            s[a] = fmaf(wT, s[a], Sc[o + (size_t)a * HS]);
        }
    }
}

__global__ __launch_bounds__(HS) void scanC_kernel(
        const float* __restrict__ r, const float* __restrict__ k,
        const float* __restrict__ v, const float* __restrict__ td,
        const float* __restrict__ tf, const float* __restrict__ S0c,
        float* __restrict__ out) {
    int bh = blockIdx.x;
    int chunk = blockIdx.y;
    int b = bh >> 5, h = bh & 31;
    int j = threadIdx.x;

    float w = expf(-expf(td[h]));
    float u = tf[h];

    float s[HS];
    size_t o = ((size_t)(chunk * 128 + bh) * HS) * HS + j;
    #pragma unroll
    for (int a = 0; a < HS; a++)
        s[a] = S0c[o + (size_t)a * HS];

    __shared__ float sr[HS], sk[HS], sv[HS];
    size_t base = (size_t)b * TTOT * CC + (size_t)h * HS;
    int t0 = chunk * TCH;

    for (int t = t0; t < t0 + TCH; t++) {
        size_t off = base + (size_t)t * CC;
        sr[j] = r[off + j];
        sk[j] = k[off + j];
        sv[j] = v[off + j];
        __syncthreads();
        float vj = sv[j];
        float kr = 0.0f, oacc = 0.0f;
        #pragma unroll
        for (int a = 0; a < HS; a++) {
            float ra = sr[a], ka = sk[a];
            kr = fmaf(ra, ka, kr);
            oacc = fmaf(ra, s[a], oacc);
            s[a] = fmaf(w, s[a], ka * vj);
        }
        oacc = fmaf(u * kr, vj, oacc);
        out[off + j] = oacc;
        __syncthreads();
    }
}

// ---------------------------------------------------------------------------
// 5) GroupNorm * gamma + beta, * g -> fp16 hi/lo of y
// ---------------------------------------------------------------------------
__global__ void gn_mul_kernel(const float* __restrict__ x, const float* __restrict__ g,
                              const float* __restrict__ gamma, const float* __restrict__ beta,
                              f16* __restrict__ yh, f16* __restrict__ yl) {
    int warp = (int)((blockIdx.x * blockDim.x + threadIdx.x) >> 5);
    int lane = threadIdx.x & 31;
    if (warp >= ROWS * NH) return;
    int row = warp >> 5;
    int h   = warp & 31;
    size_t base = (size_t)row * CC + (size_t)h * HS;

    float x0 = x[base + lane]      * 0.125f;
    float x1 = x[base + lane + 32] * 0.125f;
    float sum = x0 + x1;
    float sq  = fmaf(x0, x0, x1 * x1);
    #pragma unroll
    for (int o = 16; o; o >>= 1) {
        sum += __shfl_xor_sync(0xffffffffu, sum, o);
        sq  += __shfl_xor_sync(0xffffffffu, sq,  o);
    }
    float mu  = sum * (1.0f / 64.0f);
    float var = sq  * (1.0f / 64.0f) - mu * mu;
    float inv = rsqrtf(var + 1e-5f);

    int c0 = h * HS + lane, c1 = c0 + 32;
    float y0 = ((x0 - mu) * inv * gamma[c0] + beta[c0]) * g[base + lane];
    float y1 = ((x1 - mu) * inv * gamma[c1] + beta[c1]) * g[base + lane + 32];
    f16 hh, ll;
    split_f16(y0, hh, ll); yh[base + lane]      = hh; yl[base + lane]      = ll;
    split_f16(y1, hh, ll); yh[base + lane + 32] = hh; yl[base + lane + 32] = ll;
}

// ---------------------------------------------------------------------------
// Launcher
// ---------------------------------------------------------------------------
extern "C" void kernel_launch(void* const* d_in, const int* in_sizes, int n_in,
                              void* d_out, int out_size) {
    const float* x     = (const float*)d_in[0];
    const float* Wr    = (const float*)d_in[1];
    const float* Wk    = (const float*)d_in[2];
    const float* Wv    = (const float*)d_in[3];
    const float* Wg    = (const float*)d_in[4];
    const float* Wo    = (const float*)d_in[5];
    const float* gamma = (const float*)d_in[6];
    const float* beta  = (const float*)d_in[7];
    const float* tmk   = (const float*)d_in[8];
    const float* tmv   = (const float*)d_in[9];
    const float* tmr   = (const float*)d_in[10];
    const float* tmg   = (const float*)d_in[11];
    const float* td    = (const float*)d_in[12];
    const float* tf    = (const float*)d_in[13];
    const float* s0    = (const float*)d_in[14];
    float* out = (float*)d_out;

    static bool attr_done = false;
    if (!attr_done) {
        cudaFuncSetAttribute(tc_gemm, cudaFuncAttributeMaxDynamicSharedMemorySize, SMEM_B);
        attr_done = true;
    }

    f16 *xrh,*xrl,*xkh,*xkl,*xvh,*xvl,*xgh,*xgl,*yh,*yl;
    f16 *wrt,*wkt,*wvt,*wgt,*wot;
    float *rb,*kb,*vb,*gb,*ao,*Sc,*S0c;
    cudaGetSymbolAddress((void**)&xrh, g_xr_h); cudaGetSymbolAddress((void**)&xrl, g_xr_l);
    cudaGetSymbolAddress((void**)&xkh, g_xk_h); cudaGetSymbolAddress((void**)&xkl, g_xk_l);
    cudaGetSymbolAddress((void**)&xvh, g_xv_h); cudaGetSymbolAddress((void**)&xvl, g_xv_l);
    cudaGetSymbolAddress((void**)&xgh, g_xg_h); cudaGetSymbolAddress((void**)&xgl, g_xg_l);
    cudaGetSymbolAddress((void**)&yh,  g_y_h);  cudaGetSymbolAddress((void**)&yl,  g_y_l);
    cudaGetSymbolAddress((void**)&rb, g_r); cudaGetSymbolAddress((void**)&kb, g_k);
    cudaGetSymbolAddress((void**)&vb, g_v); cudaGetSymbolAddress((void**)&gb, g_g);
    cudaGetSymbolAddress((void**)&ao, g_ao);
    cudaGetSymbolAddress((void**)&Sc, g_Sc); cudaGetSymbolAddress((void**)&S0c, g_S0c);
    cudaGetSymbolAddress((void**)&wrt, g_WrT);
    cudaGetSymbolAddress((void**)&wkt, g_WkT);
    cudaGetSymbolAddress((void**)&wvt, g_WvT);
    cudaGetSymbolAddress((void**)&wgt, g_WgT);
    cudaGetSymbolAddress((void**)&wot, g_WoT);

    // weight transpose -> fp16
    dim3 wg2(CC / 32, CC / 32), wb2(32, 8);
    wprep_kernel<<<wg2, wb2>>>(Wr, wrt);
    wprep_kernel<<<wg2, wb2>>>(Wk, wkt);
    wprep_kernel<<<wg2, wb2>>>(Wv, wvt);
    wprep_kernel<<<wg2, wb2>>>(Wg, wgt);
    wprep_kernel<<<wg2, wb2>>>(Wo, wot);

    // token-shift mix + split
    {
        int threads = 256;
        int blocks = (int)((ELEMS + threads - 1) / threads);
        mix_kernel<<<blocks, threads>>>(x, tmk, tmv, tmr, tmg,
                                        xkh, xkl, xvh, xvl, xrh, xrl, xgh, xgl);
    }

    // projections
    dim3 gg(CC / BN, ROWS / BM);
    tc_gemm<<<gg, 256, SMEM_B>>>(xrh, xrl, wrt, rb, 0);
    tc_gemm<<<gg, 256, SMEM_B>>>(xkh, xkl, wkt, kb, 0);
    tc_gemm<<<gg, 256, SMEM_B>>>(xvh, xvl, wvt, vb, 0);
    tc_gemm<<<gg, 256, SMEM_B>>>(xgh, xgl, wgt, gb, 1);   // silu

    // chunked scan
    dim3 sg(128, NCHUNK);
    scanA_kernel<<<sg, HS>>>(kb, vb, td, Sc);
    scanB_kernel<<<128, HS>>>(s0, Sc, td, S0c);
    scanC_kernel<<<sg, HS>>>(rb, kb, vb, td, tf, S0c, ao);

    // groupnorm + gate -> y planes
    gn_mul_kernel<<<(ROWS * NH) / 8, 256>>>(ao, gb, gamma, beta, yh, yl);

    // output projection
    tc_gemm<<<gg, 256, SMEM_B>>>(yh, yl, wot, out, 0);
}